// round 3
// baseline (speedup 1.0000x reference)
#include <cuda_runtime.h>

#define NA 8400      // anchors / preds per batch
#define NC4 (NA/4)   // float4 columns = 2100
#define NG 2048      // bs*M flattened gts
#define BS 16
#define M  128
#define GT_TILE 32
#define TPB 256

__device__ __forceinline__ float frcp(float a) {
    float r; asm("rcp.approx.f32 %0, %1;" : "=f"(r) : "f"(a)); return r;
}
__device__ __forceinline__ float fsqrt_ap(float a) {
    float r; asm("sqrt.approx.f32 %0, %1;" : "=f"(r) : "f"(a)); return r;
}

// ---------------------------------------------------------------------------
// Kernel 1: distances + gious fused. 4 anchors/thread, 32 gts/block.
// ---------------------------------------------------------------------------
__global__ __launch_bounds__(TPB)
void dist_giou_kernel(const float4* __restrict__ gt,
                      const float4* __restrict__ anc,
                      float* __restrict__ dist,
                      float* __restrict__ giou)
{
    __shared__ float4 sgt[GT_TILE];
    const int c  = blockIdx.x * TPB + threadIdx.x;   // float4 column
    const int g0 = blockIdx.y * GT_TILE;

    if (threadIdx.x < GT_TILE) sgt[threadIdx.x] = gt[g0 + threadIdx.x];
    __syncthreads();

    if (c >= NC4) return;
    const int a = 4 * c;

    float Ax[4], Ay[4], Az[4], Aw[4], Acx[4], Acy[4], Aar[4], Asx[4], Asy[4];
    #pragma unroll
    for (int j = 0; j < 4; j++) {
        const float4 A = anc[a + j];
        Ax[j] = A.x; Ay[j] = A.y; Az[j] = A.z; Aw[j] = A.w;
        Acx[j] = 0.5f * (A.x + A.z);
        Acy[j] = 0.5f * (A.y + A.w);
        Asx[j] = A.z - A.x;                // anchor width
        Asy[j] = A.w - A.y;                // anchor height
        Aar[j] = Asx[j] * Asy[j];          // anchor area
    }

    float* pd = dist + (long)g0 * NA + a;
    float* pg = giou + (long)g0 * NA + a;

    #pragma unroll 4
    for (int k = 0; k < GT_TILE; k++) {
        const float4 gb = sgt[k];
        const float gcx = 0.5f * (gb.x + gb.z);
        const float gcy = 0.5f * (gb.y + gb.w);
        const float tx  = gb.z - gb.x;     // gt width
        const float ty  = gb.w - gb.y;     // gt height
        const float area1 = tx * ty;

        float dv[4], gv[4];
        #pragma unroll
        for (int j = 0; j < 4; j++) {
            // distance
            float dx = gcx - Acx[j], dy = gcy - Acy[j];
            dv[j] = fsqrt_ap(dx * dx + dy * dy);

            // intersection (keep pre-clamp widths for enclosure reuse)
            float wraw = fminf(gb.z, Az[j]) - fmaxf(gb.x, Ax[j]);
            float hraw = fminf(gb.w, Aw[j]) - fmaxf(gb.y, Ay[j]);
            float w = fmaxf(wraw, 0.0f), h = fmaxf(hraw, 0.0f);
            float ov  = w * h;
            float uni = (area1 + Aar[j]) - ov;            // >= 16 >> eps

            // enclosure via identity: ew = gt_w + anc_w - wraw
            float ew = (tx + Asx[j]) - wraw;
            float eh = (ty + Asy[j]) - hraw;

            gv[j] = fmaf(ov, frcp(uni), fmaf(uni, frcp(ew * eh), -1.0f));
        }
        __stcs((float4*)pd, make_float4(dv[0], dv[1], dv[2], dv[3]));
        __stcs((float4*)pg, make_float4(gv[0], gv[1], gv[2], gv[3]));
        pd += NA; pg += NA;
    }
}

// ---------------------------------------------------------------------------
// Kernel 2: overlaps (16 x 128 x 8400), IoU gt-vs-pred. 4 preds/thread.
// ---------------------------------------------------------------------------
__global__ __launch_bounds__(TPB)
void iou_kernel(const float4* __restrict__ gt,
                const float4* __restrict__ pred,
                float* __restrict__ out)
{
    __shared__ float4 sgt[GT_TILE];
    const int b  = blockIdx.z;
    const int c  = blockIdx.x * TPB + threadIdx.x;
    const int m0 = blockIdx.y * GT_TILE;

    if (threadIdx.x < GT_TILE) sgt[threadIdx.x] = gt[b * M + m0 + threadIdx.x];
    __syncthreads();

    if (c >= NC4) return;
    const int a = 4 * c;

    float Px[4], Py[4], Pz[4], Pw[4], Par[4];
    #pragma unroll
    for (int j = 0; j < 4; j++) {
        const float4 P = pred[b * NA + a + j];
        Px[j] = P.x; Py[j] = P.y; Pz[j] = P.z; Pw[j] = P.w;
        Par[j] = (P.z - P.x) * (P.w - P.y) + 1e-9f;
    }

    float* po = out + ((long)b * M + m0) * NA + a;

    #pragma unroll 4
    for (int k = 0; k < GT_TILE; k++) {
        const float4 gb = sgt[k];
        const float area1 = (gb.z - gb.x) * (gb.w - gb.y);

        float rv[4];
        #pragma unroll
        for (int j = 0; j < 4; j++) {
            float w = fmaxf(fminf(gb.z, Pz[j]) - fmaxf(gb.x, Px[j]), 0.0f);
            float h = fmaxf(fminf(gb.w, Pw[j]) - fmaxf(gb.y, Py[j]), 0.0f);
            float ov = w * h;
            rv[j] = ov * frcp((area1 + Par[j]) - ov);
        }
        __stcs((float4*)po, make_float4(rv[0], rv[1], rv[2], rv[3]));
        po += NA;
    }
}

extern "C" void kernel_launch(void* const* d_in, const int* in_sizes, int n_in,
                              void* d_out, int out_size)
{
    const float4* gt   = (const float4*)d_in[0];
    const float4* pred = (const float4*)d_in[1];
    const float4* anc  = (const float4*)d_in[2];

    float* dist = (float*)d_out;
    float* ovlp = dist + (long)NG * NA;
    float* giou = ovlp + (long)BS * M * NA;

    const int cblocks = (NC4 + TPB - 1) / TPB;   // 9

    dim3 g1(cblocks, NG / GT_TILE);              // 9 x 64
    dist_giou_kernel<<<g1, TPB>>>(gt, anc, dist, giou);

    dim3 g2(cblocks, M / GT_TILE, BS);           // 9 x 4 x 16
    iou_kernel<<<g2, TPB>>>(gt, pred, ovlp);
}

// round 4
// speedup vs baseline: 1.1001x; 1.1001x over previous
#include <cuda_runtime.h>

#define NA  8400        // anchors / preds per batch
#define NC4 (NA/4)      // float4 columns = 2100
#define NG  2048        // bs*M flattened gts
#define BS  16
#define M   128
#define GTT 16          // gt tile per block
#define TPB 128
#define CB  ((NC4 + TPB - 1) / TPB)      // 17 column-blocks
#define DGB (CB * (NG / GTT))            // 17*128 = 2176 dist+giou blocks
#define IOB (CB * (M / GTT) * BS)        // 17*8*16 = 2176 iou blocks

__device__ __forceinline__ float frcp(float a) {
    float r; asm("rcp.approx.f32 %0, %1;" : "=f"(r) : "f"(a)); return r;
}
__device__ __forceinline__ float fsqrt_ap(float a) {
    float r; asm("sqrt.approx.f32 %0, %1;" : "=f"(r) : "f"(a)); return r;
}

// ---------------------------------------------------------------------------
// Single fused kernel. Blocks [0, DGB) do distances+gious; [DGB, DGB+IOB) do
// gt-vs-pred IoU. Block-granular branch => no warp divergence.
// ---------------------------------------------------------------------------
__global__ __launch_bounds__(TPB, 8)
void fused_kernel(const float4* __restrict__ gt,
                  const float4* __restrict__ pred,
                  const float4* __restrict__ anc,
                  float* __restrict__ dist,
                  float* __restrict__ ovlp,
                  float* __restrict__ giou)
{
    __shared__ float4 sgt[GTT];
    const int tid = threadIdx.x;
    int blk = blockIdx.x;

    if (blk < DGB) {
        // ----- distances + gious: gt[g0..g0+16) x anchors -----
        const int cb = blk % CB;
        const int g0 = (blk / CB) * GTT;
        if (tid < GTT) sgt[tid] = gt[g0 + tid];
        __syncthreads();

        const int c = cb * TPB + tid;
        if (c >= NC4) return;
        const int a = 4 * c;

        float Ax[4], Ay[4], Az[4], Aw[4], Acx[4], Acy[4], Aar[4];
        #pragma unroll
        for (int j = 0; j < 4; j++) {
            const float4 A = anc[a + j];
            Ax[j] = A.x; Ay[j] = A.y; Az[j] = A.z; Aw[j] = A.w;
            Acx[j] = 0.5f * (A.x + A.z);
            Acy[j] = 0.5f * (A.y + A.w);
            Aar[j] = (A.z - A.x) * (A.w - A.y);
        }

        float* pd = dist + (long)g0 * NA + a;
        float* pg = giou + (long)g0 * NA + a;

        #pragma unroll 2
        for (int k = 0; k < GTT; k++) {
            const float4 gb = sgt[k];
            const float gcx = 0.5f * (gb.x + gb.z);
            const float gcy = 0.5f * (gb.y + gb.w);
            const float area1 = (gb.z - gb.x) * (gb.w - gb.y);

            float dv[4], gv[4];
            #pragma unroll
            for (int j = 0; j < 4; j++) {
                float dx = gcx - Acx[j], dy = gcy - Acy[j];
                dv[j] = fsqrt_ap(fmaf(dx, dx, dy * dy));

                float mnz = fminf(gb.z, Az[j]), mxx = fmaxf(gb.x, Ax[j]);
                float mnw = fminf(gb.w, Aw[j]), mxy = fmaxf(gb.y, Ay[j]);
                float w = fmaxf(mnz - mxx, 0.0f);
                float h = fmaxf(mnw - mxy, 0.0f);
                float ov  = w * h;
                float uni = (area1 + Aar[j]) - ov;     // >= 16 >> eps

                // enclosure: max = sum - min reuses the FMNMX results
                float ew = (gb.z + Az[j]) - mnz - ((gb.x + Ax[j]) - mxx);
                float eh = (gb.w + Aw[j]) - mnw - ((gb.y + Ay[j]) - mxy);

                gv[j] = fmaf(ov, frcp(uni), fmaf(uni, frcp(ew * eh), -1.0f));
            }
            __stcs((float4*)pd, make_float4(dv[0], dv[1], dv[2], dv[3]));
            __stcs((float4*)pg, make_float4(gv[0], gv[1], gv[2], gv[3]));
            pd += NA; pg += NA;
        }
    } else {
        // ----- overlaps: batch b, gt[m0..m0+16) x preds -----
        blk -= DGB;
        const int cb = blk % CB;
        const int r  = blk / CB;
        const int m0 = (r & 7) * GTT;     // M/GTT == 8
        const int b  = r >> 3;

        if (tid < GTT) sgt[tid] = gt[b * M + m0 + tid];
        __syncthreads();

        const int c = cb * TPB + tid;
        if (c >= NC4) return;
        const int a = 4 * c;

        float Px[4], Py[4], Pz[4], Pw[4], Par[4];
        #pragma unroll
        for (int j = 0; j < 4; j++) {
            const float4 P = pred[b * NA + a + j];
            Px[j] = P.x; Py[j] = P.y; Pz[j] = P.z; Pw[j] = P.w;
            Par[j] = (P.z - P.x) * (P.w - P.y) + 1e-9f;
        }

        float* po = ovlp + ((long)b * M + m0) * NA + a;

        #pragma unroll 2
        for (int k = 0; k < GTT; k++) {
            const float4 gb = sgt[k];
            const float area1 = (gb.z - gb.x) * (gb.w - gb.y);

            float rv[4];
            #pragma unroll
            for (int j = 0; j < 4; j++) {
                float w = fmaxf(fminf(gb.z, Pz[j]) - fmaxf(gb.x, Px[j]), 0.0f);
                float h = fmaxf(fminf(gb.w, Pw[j]) - fmaxf(gb.y, Py[j]), 0.0f);
                float ov = w * h;
                rv[j] = ov * frcp((area1 + Par[j]) - ov);
            }
            __stcs((float4*)po, make_float4(rv[0], rv[1], rv[2], rv[3]));
            po += NA;
        }
    }
}

extern "C" void kernel_launch(void* const* d_in, const int* in_sizes, int n_in,
                              void* d_out, int out_size)
{
    const float4* gt   = (const float4*)d_in[0];
    const float4* pred = (const float4*)d_in[1];
    const float4* anc  = (const float4*)d_in[2];

    float* dist = (float*)d_out;
    float* ovlp = dist + (long)NG * NA;
    float* giou = ovlp + (long)BS * M * NA;

    fused_kernel<<<DGB + IOB, TPB>>>(gt, pred, anc, dist, ovlp, giou);
}

// round 6
// speedup vs baseline: 1.1634x; 1.0576x over previous
#include <cuda_runtime.h>

#define NA  8400        // anchors / preds per batch
#define NC4 (NA/4)      // float4 columns = 2100
#define NG  2048        // bs*M flattened gts
#define BS  16
#define M   128
#define GTT 16          // gt tile per block
#define TPB 128
#define CB  ((NC4 + TPB - 1) / TPB)      // 17 column-blocks
#define DGB (CB * (NG / GTT))            // 17*128 = 2176 dist+giou blocks
#define IOB (CB * (M / GTT) * BS)        // 17*8*16 = 2176 iou blocks

typedef unsigned long long u64;

__device__ __forceinline__ float frcp(float a) {
    float r; asm("rcp.approx.f32 %0, %1;" : "=f"(r) : "f"(a)); return r;
}
__device__ __forceinline__ float fsqrt_ap(float a) {
    float r; asm("sqrt.approx.f32 %0, %1;" : "=f"(r) : "f"(a)); return r;
}
// ---- packed f32x2 helpers (sm_100+: add/sub/mul/fma only) ----
__device__ __forceinline__ u64 pack2(float lo, float hi) {
    u64 r; asm("mov.b64 %0, {%1, %2};" : "=l"(r) : "f"(lo), "f"(hi)); return r;
}
__device__ __forceinline__ void unpack2(u64 v, float& lo, float& hi) {
    asm("mov.b64 {%0, %1}, %2;" : "=f"(lo), "=f"(hi) : "l"(v));
}
__device__ __forceinline__ u64 add2(u64 a, u64 b) {
    u64 r; asm("add.rn.f32x2 %0, %1, %2;" : "=l"(r) : "l"(a), "l"(b)); return r;
}
__device__ __forceinline__ u64 sub2(u64 a, u64 b) {
    u64 r; asm("sub.rn.f32x2 %0, %1, %2;" : "=l"(r) : "l"(a), "l"(b)); return r;
}
__device__ __forceinline__ u64 mul2(u64 a, u64 b) {
    u64 r; asm("mul.rn.f32x2 %0, %1, %2;" : "=l"(r) : "l"(a), "l"(b)); return r;
}

// ---------------------------------------------------------------------------
// Fused kernel. Blocks [0, DGB): distances+gious; [DGB, DGB+IOB): IoU.
// Packed f32x2 for add/sub/mul chains; scalar FMNMX for min/max.
// ---------------------------------------------------------------------------
__global__ __launch_bounds__(TPB, 7)
void fused_kernel(const float4* __restrict__ gt,
                  const float4* __restrict__ pred,
                  const float4* __restrict__ anc,
                  float* __restrict__ dist,
                  float* __restrict__ ovlp,
                  float* __restrict__ giou)
{
    __shared__ float4 sgt[GTT];
    const int tid = threadIdx.x;
    int blk = blockIdx.x;

    if (blk < DGB) {
        // ----- distances + gious -----
        const int cb = blk % CB;
        const int g0 = (blk / CB) * GTT;
        if (tid < GTT) sgt[tid] = gt[g0 + tid];
        __syncthreads();

        const int c = cb * TPB + tid;
        if (c >= NC4) return;
        const int a = 4 * c;

        float Ax[4], Ay[4], Az[4], Aw[4];
        u64 Ac[4], Awh[4];
        float Aar[4];
        #pragma unroll
        for (int j = 0; j < 4; j++) {
            const float4 A = anc[a + j];
            Ax[j] = A.x; Ay[j] = A.y; Az[j] = A.z; Aw[j] = A.w;
            Ac[j] = pack2(0.5f * (A.x + A.z), 0.5f * (A.y + A.w));
            float aw = A.z - A.x, ah = A.w - A.y;
            Awh[j] = pack2(aw, ah);
            Aar[j] = aw * ah;
        }

        float* pd = dist + (long)g0 * NA + a;
        float* pg = giou + (long)g0 * NA + a;

        #pragma unroll 2
        for (int k = 0; k < GTT; k++) {
            const float4 gb = sgt[k];
            const u64 gc  = pack2(0.5f * (gb.x + gb.z), 0.5f * (gb.y + gb.w));
            const float tx = gb.z - gb.x, ty = gb.w - gb.y;
            const u64 gwh = pack2(tx, ty);
            const float area1 = tx * ty;

            float dv[4], gv[4];
            #pragma unroll
            for (int j = 0; j < 4; j++) {
                // distance: packed diff+square, scalar horizontal add
                u64 d2 = sub2(gc, Ac[j]);
                d2 = mul2(d2, d2);
                float dxx, dyy; unpack2(d2, dxx, dyy);
                dv[j] = fsqrt_ap(dxx + dyy);

                // intersection corners (scalar FMNMX, min count)
                float mxx = fmaxf(gb.x, Ax[j]), mxy = fmaxf(gb.y, Ay[j]);
                float mnz = fminf(gb.z, Az[j]), mnw = fminf(gb.w, Aw[j]);
                // pre-clamp wh (packed) reused for enclosure identity
                u64 whr = sub2(pack2(mnz, mnw), pack2(mxx, mxy));
                float wraw, hraw; unpack2(whr, wraw, hraw);
                float ov  = fmaxf(wraw, 0.0f) * fmaxf(hraw, 0.0f);
                float uni = (area1 + Aar[j]) - ov;          // >= 16 >> eps

                // enclosure: ewh = gwh + awh - whraw (packed)
                u64 ewh = sub2(add2(gwh, Awh[j]), whr);
                float ew, eh; unpack2(ewh, ew, eh);

                gv[j] = fmaf(ov, frcp(uni), fmaf(uni, frcp(ew * eh), -1.0f));
            }
            __stcs((float4*)pd, make_float4(dv[0], dv[1], dv[2], dv[3]));
            __stcs((float4*)pg, make_float4(gv[0], gv[1], gv[2], gv[3]));
            pd += NA; pg += NA;
        }
    } else {
        // ----- overlaps (gt vs pred IoU) -----
        blk -= DGB;
        const int cb = blk % CB;
        const int r  = blk / CB;
        const int m0 = (r & 7) * GTT;     // M/GTT == 8
        const int b  = r >> 3;

        if (tid < GTT) sgt[tid] = gt[b * M + m0 + tid];
        __syncthreads();

        const int c = cb * TPB + tid;
        if (c >= NC4) return;
        const int a = 4 * c;

        float Px[4], Py[4], Pz[4], Pw[4], Par[4];
        #pragma unroll
        for (int j = 0; j < 4; j++) {
            const float4 P = pred[b * NA + a + j];
            Px[j] = P.x; Py[j] = P.y; Pz[j] = P.z; Pw[j] = P.w;
            Par[j] = (P.z - P.x) * (P.w - P.y) + 1e-9f;
        }

        float* po = ovlp + ((long)b * M + m0) * NA + a;

        #pragma unroll 2
        for (int k = 0; k < GTT; k++) {
            const float4 gb = sgt[k];
            const float area1 = (gb.z - gb.x) * (gb.w - gb.y);

            float rv[4];
            #pragma unroll
            for (int j = 0; j < 4; j++) {
                float mxx = fmaxf(gb.x, Px[j]), mxy = fmaxf(gb.y, Py[j]);
                float mnz = fminf(gb.z, Pz[j]), mnw = fminf(gb.w, Pw[j]);
                u64 whr = sub2(pack2(mnz, mnw), pack2(mxx, mxy));
                float wraw, hraw; unpack2(whr, wraw, hraw);
                float ov = fmaxf(wraw, 0.0f) * fmaxf(hraw, 0.0f);
                rv[j] = ov * frcp((area1 + Par[j]) - ov);
            }
            __stcs((float4*)po, make_float4(rv[0], rv[1], rv[2], rv[3]));
            po += NA;
        }
    }
}

extern "C" void kernel_launch(void* const* d_in, const int* in_sizes, int n_in,
                              void* d_out, int out_size)
{
    const float4* gt   = (const float4*)d_in[0];
    const float4* pred = (const float4*)d_in[1];
    const float4* anc  = (const float4*)d_in[2];

    float* dist = (float*)d_out;
    float* ovlp = dist + (long)NG * NA;
    float* giou = ovlp + (long)BS * M * NA;

    fused_kernel<<<DGB + IOB, TPB>>>(gt, pred, anc, dist, ovlp, giou);
}